// round 1
// baseline (speedup 1.0000x reference)
#include <cuda_runtime.h>
#include <cuda_bf16.h>
#include <math.h>

#define NN  50000   // nodes
#define EE  800000  // edges
#define LL  100000  // label edges
#define HH  8       // heads
#define FD  32      // hidden
#define HC  256     // H*C

// ---------------- scratch (device globals; no allocation in kernel_launch) ----
__device__ float g_x[NN * FD];        // node features entering a GAT layer
__device__ float g_h[(size_t)NN * HC];// h = x @ W
__device__ float g_alsrc[NN * HH];
__device__ float g_aldst[NN * HH];
__device__ float g_alpha[(size_t)EE * HH]; // alpha, then exp(alpha - amax)
__device__ int   g_amax[NN * HH];     // ordered-int encoded float max
__device__ float g_denom[NN * HH];
__device__ float g_agg[(size_t)NN * HC];
__device__ float g_x5[NN * HH];
__device__ float g_Psrc[2][FD * HH];
__device__ float g_Pdst[2][FD * HH];
__device__ float g_M[2][HH * HH];

// ---------------- helpers ------------------------------------------------------
__device__ __forceinline__ int f2o(float f) {          // monotone float -> int
    int i = __float_as_int(f);
    return i >= 0 ? i : (i ^ 0x7fffffff);
}
__device__ __forceinline__ float o2f(int o) {
    return __int_as_float(o >= 0 ? o : (o ^ 0x7fffffff));
}
__device__ __forceinline__ void red_add_v4(float* addr, float4 v) {
    asm volatile("red.global.add.v4.f32 [%0], {%1, %2, %3, %4};"
                 :: "l"(addr), "f"(v.x), "f"(v.y), "f"(v.z), "f"(v.w)
                 : "memory");
}

// ---------------- tiny precompute: P_src, P_dst [32,8], M [8,8] ---------------
__global__ void k_precompute(const float* __restrict__ W,
                             const float* __restrict__ a_s,
                             const float* __restrict__ a_d,
                             const float* __restrict__ We,
                             const float* __restrict__ a_e,
                             int layer)
{
    int t = threadIdx.x;           // 256 threads
    int f = t >> 3, h = t & 7;
    float ss = 0.f, sd = 0.f;
    #pragma unroll 8
    for (int c = 0; c < FD; c++) {
        float w = W[f * HC + h * FD + c];
        ss = fmaf(w, a_s[h * FD + c], ss);
        sd = fmaf(w, a_d[h * FD + c], sd);
    }
    g_Psrc[layer][f * HH + h] = ss;
    g_Pdst[layer][f * HH + h] = sd;
    if (t < 64) {
        int k = t >> 3;
        float sm = 0.f;
        #pragma unroll 8
        for (int c = 0; c < FD; c++)
            sm = fmaf(We[k * HC + h * FD + c], a_e[h * FD + c], sm);
        g_M[layer][k * HH + h] = sm;
    }
}

// ---------------- reset kernels ------------------------------------------------
__global__ void k_init(void) {
    int i = blockIdx.x * 256 + threadIdx.x;
    if (i < NN * HH) { g_amax[i] = (int)0x80000000; g_denom[i] = 0.f; }
}
__global__ void k_zero_agg(void) {
    int i = blockIdx.x * 256 + threadIdx.x;
    if (i < NN * (HC / 4))
        ((float4*)g_agg)[i] = make_float4(0.f, 0.f, 0.f, 0.f);
}

// ---------------- node transform: h = x@W, al_src = x@Psrc, al_dst = x@Pdst ----
__global__ void __launch_bounds__(256)
k_node(const float* __restrict__ xin, const int* __restrict__ ids,
       const float* __restrict__ W, int layer)
{
    __shared__ float Ws[FD * HC];      // 32KB
    __shared__ float xs[32 * 36];      // 32 nodes, padded stride 36
    __shared__ float Ps[FD * HH], Pd[FD * HH];
    int t  = threadIdx.x;
    int n0 = blockIdx.x * 32;

    for (int i = t; i < FD * HC; i += 256) Ws[i] = W[i];
    Ps[t] = g_Psrc[layer][t];
    Pd[t] = g_Pdst[layer][t];
    const float* xp = xin ? xin : g_x;
    for (int i = t; i < 32 * FD; i += 256) {
        int n = i >> 5, k = i & 31;
        int node = n0 + n;
        float v = 0.f;
        if (node < NN) {
            int r = ids ? ids[node] : node;
            v = xp[(size_t)r * FD + k];
        }
        xs[n * 36 + k] = v;
    }
    __syncthreads();

    // GEMM: thread t owns output column c=t for 32 nodes
    float acc[32];
    #pragma unroll
    for (int n = 0; n < 32; n++) acc[n] = 0.f;
    #pragma unroll
    for (int kk = 0; kk < 8; kk++) {
        float w0 = Ws[(kk * 4 + 0) * HC + t];
        float w1 = Ws[(kk * 4 + 1) * HC + t];
        float w2 = Ws[(kk * 4 + 2) * HC + t];
        float w3 = Ws[(kk * 4 + 3) * HC + t];
        #pragma unroll
        for (int n = 0; n < 32; n++) {
            float4 xv = *(const float4*)&xs[n * 36 + kk * 4];
            acc[n] = fmaf(xv.x, w0, acc[n]);
            acc[n] = fmaf(xv.y, w1, acc[n]);
            acc[n] = fmaf(xv.z, w2, acc[n]);
            acc[n] = fmaf(xv.w, w3, acc[n]);
        }
    }
    #pragma unroll
    for (int n = 0; n < 32; n++)
        if (n0 + n < NN) g_h[(size_t)(n0 + n) * HC + t] = acc[n];

    // attention logits
    {
        int n = t >> 3, h = t & 7;
        if (n0 + n < NN) {
            float ss = 0.f, sd = 0.f;
            #pragma unroll
            for (int k = 0; k < FD; k++) {
                float xv = xs[n * 36 + k];
                ss = fmaf(xv, Ps[k * HH + h], ss);
                sd = fmaf(xv, Pd[k * HH + h], sd);
            }
            g_alsrc[(n0 + n) * HH + h] = ss;
            g_aldst[(n0 + n) * HH + h] = sd;
        }
    }
}

// ---------------- edge: alpha = lrelu(al_src[s]+al_dst[d]+ea@M), segment max ---
__global__ void __launch_bounds__(256)
k_edge_alpha(const int* __restrict__ src, const int* __restrict__ dst,
             const float* __restrict__ ea, int layer)
{
    __shared__ float Ms[64];
    if (threadIdx.x < 64) Ms[threadIdx.x] = g_M[layer][threadIdx.x];
    __syncthreads();
    int e = blockIdx.x * 256 + threadIdx.x;
    if (e >= EE) return;
    int s = src[e], d = dst[e];

    float4 e0 = *(const float4*)(ea + (size_t)e * 8);
    float4 e1 = *(const float4*)(ea + (size_t)e * 8 + 4);
    float4 s0 = *(const float4*)(g_alsrc + (size_t)s * 8);
    float4 s1 = *(const float4*)(g_alsrc + (size_t)s * 8 + 4);
    float4 d0 = *(const float4*)(g_aldst + (size_t)d * 8);
    float4 d1 = *(const float4*)(g_aldst + (size_t)d * 8 + 4);

    float al[8] = { s0.x + d0.x, s0.y + d0.y, s0.z + d0.z, s0.w + d0.w,
                    s1.x + d1.x, s1.y + d1.y, s1.z + d1.z, s1.w + d1.w };
    float ev[8] = { e0.x, e0.y, e0.z, e0.w, e1.x, e1.y, e1.z, e1.w };
    #pragma unroll
    for (int k = 0; k < 8; k++)
        #pragma unroll
        for (int h = 0; h < 8; h++)
            al[h] = fmaf(ev[k], Ms[k * 8 + h], al[h]);
    #pragma unroll
    for (int h = 0; h < 8; h++) al[h] = al[h] > 0.f ? al[h] : 0.2f * al[h];

    *(float4*)(g_alpha + (size_t)e * 8)     = make_float4(al[0], al[1], al[2], al[3]);
    *(float4*)(g_alpha + (size_t)e * 8 + 4) = make_float4(al[4], al[5], al[6], al[7]);
    int* am = g_amax + (size_t)d * 8;
    #pragma unroll
    for (int h = 0; h < 8; h++) atomicMax(&am[h], f2o(al[h]));
}

// ---------------- edge: ex = exp(alpha - amax[d]); denom[d] += ex --------------
__global__ void __launch_bounds__(256)
k_edge_ex(const int* __restrict__ dst)
{
    int e = blockIdx.x * 256 + threadIdx.x;
    if (e >= EE) return;
    int d = dst[e];
    int4 m0 = *(const int4*)(g_amax + (size_t)d * 8);
    int4 m1 = *(const int4*)(g_amax + (size_t)d * 8 + 4);
    float4 a0 = *(const float4*)(g_alpha + (size_t)e * 8);
    float4 a1 = *(const float4*)(g_alpha + (size_t)e * 8 + 4);
    float4 x0, x1;
    x0.x = expf(a0.x - o2f(m0.x));  x0.y = expf(a0.y - o2f(m0.y));
    x0.z = expf(a0.z - o2f(m0.z));  x0.w = expf(a0.w - o2f(m0.w));
    x1.x = expf(a1.x - o2f(m1.x));  x1.y = expf(a1.y - o2f(m1.y));
    x1.z = expf(a1.z - o2f(m1.z));  x1.w = expf(a1.w - o2f(m1.w));
    *(float4*)(g_alpha + (size_t)e * 8)     = x0;
    *(float4*)(g_alpha + (size_t)e * 8 + 4) = x1;
    red_add_v4(g_denom + (size_t)d * 8,     x0);
    red_add_v4(g_denom + (size_t)d * 8 + 4, x1);
}

// ---------------- heavy: out[d] += h[s,h,:] * w[e,h]  (one warp per edge) ------
__global__ void __launch_bounds__(256)
k_agg(const int* __restrict__ src, const int* __restrict__ dst)
{
    int gw   = (blockIdx.x * 256 + threadIdx.x) >> 5;
    int lane = threadIdx.x & 31;
    if (gw >= EE) return;
    int e = gw;
    int s = src[e], d = dst[e];

    float w_l = 0.f;
    if (lane < 8) {
        float ex  = g_alpha[(size_t)e * 8 + lane];
        float den = g_denom[(size_t)d * 8 + lane];
        w_l = ex / (den + 1e-16f);
    }
    float w0 = __shfl_sync(0xffffffffu, w_l, lane >> 3);
    float w1 = __shfl_sync(0xffffffffu, w_l, 4 + (lane >> 3));

    const float4* hs = (const float4*)(g_h + (size_t)s * HC);
    float* po = g_agg + (size_t)d * HC;
    float4 v0 = hs[lane];
    float4 v1 = hs[lane + 32];
    v0.x *= w0; v0.y *= w0; v0.z *= w0; v0.w *= w0;
    v1.x *= w1; v1.y *= w1; v1.z *= w1; v1.w *= w1;
    red_add_v4(po + lane * 4, v0);
    red_add_v4(po + (lane + 32) * 4, v1);
}

// ---------------- epilogue: y = relu(agg + b) @ LW + lb ------------------------
template <int NJ>
__global__ void __launch_bounds__(256)
k_epi(const float* __restrict__ bias, const float* __restrict__ LW,
      const float* __restrict__ lb)
{
    constexpr int NODES = 256 / NJ;
    __shared__ float rows[NODES][260];
    __shared__ float LWs[HC * NJ];
    int t  = threadIdx.x;
    int n0 = blockIdx.x * NODES;

    for (int i = t; i < HC * NJ; i += 256) LWs[i] = LW[i];
    for (int i = t; i < NODES * HC; i += 256) {
        int n = i >> 8, c = i & 255;
        float v = 0.f;
        if (n0 + n < NN) v = g_agg[(size_t)(n0 + n) * HC + c] + bias[c];
        rows[n][c] = fmaxf(v, 0.f);
    }
    __syncthreads();

    int n = t / NJ, j = t % NJ;
    if (n0 + n < NN) {
        float acc = lb[j];
        #pragma unroll 8
        for (int c = 0; c < HC; c++)
            acc = fmaf(rows[n][c], LWs[c * NJ + j], acc);
        if (NJ == 32) g_x [(size_t)(n0 + n) * 32 + j] = acc;
        else          g_x5[(size_t)(n0 + n) * 8  + j] = acc;
    }
}

// ---------------- classifier over label edges ---------------------------------
__global__ void __launch_bounds__(256)
k_clf(const int* __restrict__ eli, const float* __restrict__ ela,
      const float* __restrict__ cW, const float* __restrict__ cb,
      float* __restrict__ outp)
{
    __shared__ float Ws[128], Bs[8];
    if (threadIdx.x < 128) Ws[threadIdx.x] = cW[threadIdx.x];
    if (threadIdx.x < 8)   Bs[threadIdx.x] = cb[threadIdx.x];
    __syncthreads();
    int l = blockIdx.x * 256 + threadIdx.x;
    if (l >= LL) return;
    int u = eli[l], m = eli[LL + l];

    float4 u0 = *(const float4*)(g_x5 + (size_t)u * 8);
    float4 u1 = *(const float4*)(g_x5 + (size_t)u * 8 + 4);
    float4 m0 = *(const float4*)(g_x5 + (size_t)m * 8);
    float4 m1 = *(const float4*)(g_x5 + (size_t)m * 8 + 4);
    float4 a0 = *(const float4*)(ela + (size_t)l * 8);
    float4 a1 = *(const float4*)(ela + (size_t)l * 8 + 4);
    float xu[8] = { u0.x, u0.y, u0.z, u0.w, u1.x, u1.y, u1.z, u1.w };
    float xm[8] = { m0.x, m0.y, m0.z, m0.w, m1.x, m1.y, m1.z, m1.w };
    float ev[8] = { a0.x, a0.y, a0.z, a0.w, a1.x, a1.y, a1.z, a1.w };

    float dot = 0.f;
    #pragma unroll
    for (int j = 0; j < 8; j++) {
        float fu = Bs[j];
        #pragma unroll
        for (int k = 0; k < 8; k++) fu = fmaf(xu[k], Ws[k * 8 + j], fu);
        #pragma unroll
        for (int k = 0; k < 8; k++) fu = fmaf(ev[k], Ws[(8 + k) * 8 + j], fu);
        dot = fmaf(fu, xm[j], dot);
    }
    outp[l] = 1.f / (1.f + expf(-dot));
}

// ---------------- launch -------------------------------------------------------
extern "C" void kernel_launch(void* const* d_in, const int* in_sizes, int n_in,
                              void* d_out, int out_size)
{
    const int*   node_ids = (const int*)d_in[0];
    const int*   ei   = (const int*)d_in[1];
    const int*   eli  = (const int*)d_in[2];
    const float* ea   = (const float*)d_in[4];
    const float* ela  = (const float*)d_in[5];
    const float* emb  = (const float*)d_in[6];
    const float* W1   = (const float*)d_in[7];
    const float* as1  = (const float*)d_in[8];
    const float* ad1  = (const float*)d_in[9];
    const float* We1  = (const float*)d_in[10];
    const float* ae1  = (const float*)d_in[11];
    const float* b1   = (const float*)d_in[12];
    const float* l1W  = (const float*)d_in[13];
    const float* l1b  = (const float*)d_in[14];
    const float* W2   = (const float*)d_in[15];
    const float* as2  = (const float*)d_in[16];
    const float* ad2  = (const float*)d_in[17];
    const float* We2  = (const float*)d_in[18];
    const float* ae2  = (const float*)d_in[19];
    const float* b2   = (const float*)d_in[20];
    const float* l5W  = (const float*)d_in[21];
    const float* l5b  = (const float*)d_in[22];
    const float* cW   = (const float*)d_in[23];
    const float* cb   = (const float*)d_in[24];
    float* out = (float*)d_out;

    const int* srce = ei;
    const int* dste = ei + EE;

    const int GB_NODE  = (NN + 31) / 32;           // 1563
    const int GB_EDGE  = (EE + 255) / 256;         // 3125
    const int GB_AGG   = (EE + 7) / 8;             // 100000
    const int GB_INIT  = (NN * HH + 255) / 256;    // 1563
    const int GB_ZAGG  = (NN * (HC / 4) + 255) / 256; // 12500

    k_precompute<<<1, 256>>>(W1, as1, ad1, We1, ae1, 0);
    k_precompute<<<1, 256>>>(W2, as2, ad2, We2, ae2, 1);

    // ---- layer 1 ----
    k_init<<<GB_INIT, 256>>>();
    k_zero_agg<<<GB_ZAGG, 256>>>();
    k_node<<<GB_NODE, 256>>>(emb, node_ids, W1, 0);
    k_edge_alpha<<<GB_EDGE, 256>>>(srce, dste, ea, 0);
    k_edge_ex<<<GB_EDGE, 256>>>(dste);
    k_agg<<<GB_AGG, 256>>>(srce, dste);
    k_epi<32><<<(NN + 7) / 8, 256>>>(b1, l1W, l1b);

    // ---- layer 2 ----
    k_init<<<GB_INIT, 256>>>();
    k_zero_agg<<<GB_ZAGG, 256>>>();
    k_node<<<GB_NODE, 256>>>(nullptr, nullptr, W2, 1);
    k_edge_alpha<<<GB_EDGE, 256>>>(srce, dste, ea, 1);
    k_edge_ex<<<GB_EDGE, 256>>>(dste);
    k_agg<<<GB_AGG, 256>>>(srce, dste);
    k_epi<8><<<(NN + 31) / 32, 256>>>(b2, l5W, l5b);

    // ---- classifier ----
    k_clf<<<(LL + 255) / 256, 256>>>(eli, ela, cW, cb, out);
}

// round 2
// speedup vs baseline: 1.1663x; 1.1663x over previous
#include <cuda_runtime.h>
#include <cuda_bf16.h>
#include <math.h>

#define NN  50000   // nodes
#define EE  800000  // edges
#define LL  100000  // label edges
#define HH  8       // heads
#define FD  32      // hidden
#define HC  256     // H*C

// ---------------- scratch (device globals; no allocation in kernel_launch) ----
__device__ float g_x[NN * FD];          // node features entering a GAT layer
__device__ float g_h[(size_t)NN * HC];  // h = x @ W
__device__ float g_alsrc[NN * HH];
__device__ float g_aldst[NN * HH];
__device__ float g_alpha[(size_t)EE * HH]; // alpha (CSR order), then normalized w
__device__ float g_agg[(size_t)NN * HC];
__device__ float g_x5[NN * HH];
__device__ float g_Psrc[2][FD * HH];
__device__ float g_Pdst[2][FD * HH];
__device__ float g_M[2][HH * HH];
// CSR by destination
__device__ int g_deg[NN];
__device__ int g_rowptr[NN + 1];
__device__ int g_cursor[NN];
__device__ int g_srcp[EE];   // src node per CSR slot
__device__ int g_dstp[EE];   // dst node per CSR slot
__device__ int g_eorig[EE];  // original edge id per CSR slot

// ---------------- tiny precompute: P_src, P_dst [32,8], M [8,8] ---------------
__global__ void k_precompute(const float* __restrict__ W,
                             const float* __restrict__ a_s,
                             const float* __restrict__ a_d,
                             const float* __restrict__ We,
                             const float* __restrict__ a_e,
                             int layer)
{
    int t = threadIdx.x;           // 256 threads
    int f = t >> 3, h = t & 7;
    float ss = 0.f, sd = 0.f;
    #pragma unroll 8
    for (int c = 0; c < FD; c++) {
        float w = W[f * HC + h * FD + c];
        ss = fmaf(w, a_s[h * FD + c], ss);
        sd = fmaf(w, a_d[h * FD + c], sd);
    }
    g_Psrc[layer][f * HH + h] = ss;
    g_Pdst[layer][f * HH + h] = sd;
    if (t < 64) {
        int k = t >> 3;
        float sm = 0.f;
        #pragma unroll 8
        for (int c = 0; c < FD; c++)
            sm = fmaf(We[k * HC + h * FD + c], a_e[h * FD + c], sm);
        g_M[layer][k * HH + h] = sm;
    }
}

// ---------------- CSR build -----------------------------------------------------
__global__ void k_zero_deg(void) {
    int i = blockIdx.x * 256 + threadIdx.x;
    if (i < NN) g_deg[i] = 0;
}
__global__ void k_hist(const int* __restrict__ dst) {
    int e = blockIdx.x * 256 + threadIdx.x;
    if (e < EE) atomicAdd(&g_deg[dst[e]], 1);
}
__global__ void __launch_bounds__(1024)
k_scan(void) {
    const int CH = (NN + 1023) / 1024;   // 49
    __shared__ int sums[1024];
    int t = threadIdx.x;
    int base = t * CH;
    int s = 0;
    for (int i = 0; i < CH; i++) {
        int idx = base + i;
        if (idx < NN) s += g_deg[idx];
    }
    sums[t] = s;
    __syncthreads();
    for (int off = 1; off < 1024; off <<= 1) {
        int v = (t >= off) ? sums[t - off] : 0;
        __syncthreads();
        sums[t] += v;
        __syncthreads();
    }
    int run = (t > 0) ? sums[t - 1] : 0;   // exclusive prefix of this chunk
    for (int i = 0; i < CH; i++) {
        int idx = base + i;
        if (idx < NN) {
            g_rowptr[idx] = run;
            g_cursor[idx] = run;
            run += g_deg[idx];
        }
    }
    if (t == 1023) g_rowptr[NN] = run;
}
__global__ void k_scatter(const int* __restrict__ src, const int* __restrict__ dst) {
    int e = blockIdx.x * 256 + threadIdx.x;
    if (e >= EE) return;
    int d = dst[e];
    int slot = atomicAdd(&g_cursor[d], 1);
    g_srcp[slot]  = src[e];
    g_dstp[slot]  = d;
    g_eorig[slot] = e;
}

// ---------------- node transform: h = x@W, al_src = x@Psrc, al_dst = x@Pdst ----
__global__ void __launch_bounds__(256)
k_node(const float* __restrict__ xin, const int* __restrict__ ids,
       const float* __restrict__ W, int layer)
{
    __shared__ float Ws[FD * HC];      // 32KB
    __shared__ float xs[32 * 36];      // 32 nodes, padded stride 36
    __shared__ float Ps[FD * HH], Pd[FD * HH];
    int t  = threadIdx.x;
    int n0 = blockIdx.x * 32;

    for (int i = t; i < FD * HC; i += 256) Ws[i] = W[i];
    Ps[t] = g_Psrc[layer][t];
    Pd[t] = g_Pdst[layer][t];
    const float* xp = xin ? xin : g_x;
    for (int i = t; i < 32 * FD; i += 256) {
        int n = i >> 5, k = i & 31;
        int node = n0 + n;
        float v = 0.f;
        if (node < NN) {
            int r = ids ? ids[node] : node;
            v = xp[(size_t)r * FD + k];
        }
        xs[n * 36 + k] = v;
    }
    __syncthreads();

    float acc[32];
    #pragma unroll
    for (int n = 0; n < 32; n++) acc[n] = 0.f;
    #pragma unroll
    for (int kk = 0; kk < 8; kk++) {
        float w0 = Ws[(kk * 4 + 0) * HC + t];
        float w1 = Ws[(kk * 4 + 1) * HC + t];
        float w2 = Ws[(kk * 4 + 2) * HC + t];
        float w3 = Ws[(kk * 4 + 3) * HC + t];
        #pragma unroll
        for (int n = 0; n < 32; n++) {
            float4 xv = *(const float4*)&xs[n * 36 + kk * 4];
            acc[n] = fmaf(xv.x, w0, acc[n]);
            acc[n] = fmaf(xv.y, w1, acc[n]);
            acc[n] = fmaf(xv.z, w2, acc[n]);
            acc[n] = fmaf(xv.w, w3, acc[n]);
        }
    }
    #pragma unroll
    for (int n = 0; n < 32; n++)
        if (n0 + n < NN) g_h[(size_t)(n0 + n) * HC + t] = acc[n];

    {
        int n = t >> 3, h = t & 7;
        if (n0 + n < NN) {
            float ss = 0.f, sd = 0.f;
            #pragma unroll
            for (int k = 0; k < FD; k++) {
                float xv = xs[n * 36 + k];
                ss = fmaf(xv, Ps[k * HH + h], ss);
                sd = fmaf(xv, Pd[k * HH + h], sd);
            }
            g_alsrc[(n0 + n) * HH + h] = ss;
            g_aldst[(n0 + n) * HH + h] = sd;
        }
    }
}

// ---------------- edge alpha (CSR order): lrelu(al_src[s]+al_dst[d]+ea@M) -------
__global__ void __launch_bounds__(256)
k_edge_alpha(const float* __restrict__ ea, int layer)
{
    __shared__ float Ms[64];
    if (threadIdx.x < 64) Ms[threadIdx.x] = g_M[layer][threadIdx.x];
    __syncthreads();
    int p = blockIdx.x * 256 + threadIdx.x;
    if (p >= EE) return;
    int s  = g_srcp[p];
    int d  = g_dstp[p];
    int eo = g_eorig[p];

    float4 e0 = *(const float4*)(ea + (size_t)eo * 8);
    float4 e1 = *(const float4*)(ea + (size_t)eo * 8 + 4);
    float4 s0 = *(const float4*)(g_alsrc + (size_t)s * 8);
    float4 s1 = *(const float4*)(g_alsrc + (size_t)s * 8 + 4);
    float4 d0 = *(const float4*)(g_aldst + (size_t)d * 8);
    float4 d1 = *(const float4*)(g_aldst + (size_t)d * 8 + 4);

    float al[8] = { s0.x + d0.x, s0.y + d0.y, s0.z + d0.z, s0.w + d0.w,
                    s1.x + d1.x, s1.y + d1.y, s1.z + d1.z, s1.w + d1.w };
    float ev[8] = { e0.x, e0.y, e0.z, e0.w, e1.x, e1.y, e1.z, e1.w };
    #pragma unroll
    for (int k = 0; k < 8; k++)
        #pragma unroll
        for (int h = 0; h < 8; h++)
            al[h] = fmaf(ev[k], Ms[k * 8 + h], al[h]);
    #pragma unroll
    for (int h = 0; h < 8; h++) al[h] = al[h] > 0.f ? al[h] : 0.2f * al[h];

    *(float4*)(g_alpha + (size_t)p * 8)     = make_float4(al[0], al[1], al[2], al[3]);
    *(float4*)(g_alpha + (size_t)p * 8 + 4) = make_float4(al[4], al[5], al[6], al[7]);
}

// ---------------- per-node segment softmax (warp per node, contiguous slots) ---
__global__ void __launch_bounds__(256)
k_softmax(void)
{
    int n    = (blockIdx.x * 256 + threadIdx.x) >> 5;
    int lane = threadIdx.x & 31;
    if (n >= NN) return;
    int r0 = g_rowptr[n], r1 = g_rowptr[n + 1];
    int deg = r1 - r0;
    if (deg == 0) return;

    int h  = lane & 7;       // head
    int eg = lane >> 3;      // edge group 0..3

    // phase A: per-head max
    float m = -INFINITY;
    for (int i = eg; i < deg; i += 4)
        m = fmaxf(m, g_alpha[(size_t)(r0 + i) * 8 + h]);
    m = fmaxf(m, __shfl_xor_sync(0xffffffffu, m, 8));
    m = fmaxf(m, __shfl_xor_sync(0xffffffffu, m, 16));

    // phase B: denom
    float s = 0.f;
    for (int i = eg; i < deg; i += 4)
        s += expf(g_alpha[(size_t)(r0 + i) * 8 + h] - m);
    s += __shfl_xor_sync(0xffffffffu, s, 8);
    s += __shfl_xor_sync(0xffffffffu, s, 16);
    float rinv = 1.f / (s + 1e-16f);

    // phase C: write normalized weights in place
    for (int i = eg; i < deg; i += 4) {
        size_t idx = (size_t)(r0 + i) * 8 + h;
        g_alpha[idx] = expf(g_alpha[idx] - m) * rinv;
    }
}

// ---------------- heavy: agg[n] = sum_{edges->n} h[src] * w  (warp per node) ---
__global__ void __launch_bounds__(256)
k_agg_csr(void)
{
    int n    = (blockIdx.x * 256 + threadIdx.x) >> 5;
    int lane = threadIdx.x & 31;
    if (n >= NN) return;
    int r0 = g_rowptr[n], r1 = g_rowptr[n + 1];

    float4 acc0 = make_float4(0.f, 0.f, 0.f, 0.f);
    float4 acc1 = make_float4(0.f, 0.f, 0.f, 0.f);

    int hb0 = lane >> 3;        // head for first float4 (cols 4*lane)
    int hb1 = 4 + (lane >> 3);  // head for second float4 (cols 128+4*lane)

    // software pipeline: prefetch next edge's src + weight
    int   s_cur = 0;
    float w_cur = 0.f;
    if (r0 < r1) {
        s_cur = g_srcp[r0];
        w_cur = (lane < 8) ? g_alpha[(size_t)r0 * 8 + lane] : 0.f;
    }
    for (int p = r0; p < r1; p++) {
        int   s_nxt = 0;
        float w_nxt = 0.f;
        if (p + 1 < r1) {
            s_nxt = g_srcp[p + 1];
            w_nxt = (lane < 8) ? g_alpha[(size_t)(p + 1) * 8 + lane] : 0.f;
        }
        float w0 = __shfl_sync(0xffffffffu, w_cur, hb0);
        float w1 = __shfl_sync(0xffffffffu, w_cur, hb1);
        const float4* hs = (const float4*)(g_h + (size_t)s_cur * HC);
        float4 v0 = hs[lane];
        float4 v1 = hs[lane + 32];
        acc0.x = fmaf(v0.x, w0, acc0.x);
        acc0.y = fmaf(v0.y, w0, acc0.y);
        acc0.z = fmaf(v0.z, w0, acc0.z);
        acc0.w = fmaf(v0.w, w0, acc0.w);
        acc1.x = fmaf(v1.x, w1, acc1.x);
        acc1.y = fmaf(v1.y, w1, acc1.y);
        acc1.z = fmaf(v1.z, w1, acc1.z);
        acc1.w = fmaf(v1.w, w1, acc1.w);
        s_cur = s_nxt;
        w_cur = w_nxt;
    }
    float4* po = (float4*)(g_agg + (size_t)n * HC);
    po[lane]      = acc0;
    po[lane + 32] = acc1;
}

// ---------------- epilogue: y = relu(agg + b) @ LW + lb ------------------------
template <int NJ>
__global__ void __launch_bounds__(256)
k_epi(const float* __restrict__ bias, const float* __restrict__ LW,
      const float* __restrict__ lb)
{
    constexpr int NODES = 256 / NJ;
    __shared__ float rows[NODES][260];
    __shared__ float LWs[HC * NJ];
    int t  = threadIdx.x;
    int n0 = blockIdx.x * NODES;

    for (int i = t; i < HC * NJ; i += 256) LWs[i] = LW[i];
    for (int i = t; i < NODES * HC; i += 256) {
        int n = i >> 8, c = i & 255;
        float v = 0.f;
        if (n0 + n < NN) v = g_agg[(size_t)(n0 + n) * HC + c] + bias[c];
        rows[n][c] = fmaxf(v, 0.f);
    }
    __syncthreads();

    int n = t / NJ, j = t % NJ;
    if (n0 + n < NN) {
        float acc = lb[j];
        #pragma unroll 8
        for (int c = 0; c < HC; c++)
            acc = fmaf(rows[n][c], LWs[c * NJ + j], acc);
        if (NJ == 32) g_x [(size_t)(n0 + n) * 32 + j] = acc;
        else          g_x5[(size_t)(n0 + n) * 8  + j] = acc;
    }
}

// ---------------- classifier over label edges ---------------------------------
__global__ void __launch_bounds__(256)
k_clf(const int* __restrict__ eli, const float* __restrict__ ela,
      const float* __restrict__ cW, const float* __restrict__ cb,
      float* __restrict__ outp)
{
    __shared__ float Ws[128], Bs[8];
    if (threadIdx.x < 128) Ws[threadIdx.x] = cW[threadIdx.x];
    if (threadIdx.x < 8)   Bs[threadIdx.x] = cb[threadIdx.x];
    __syncthreads();
    int l = blockIdx.x * 256 + threadIdx.x;
    if (l >= LL) return;
    int u = eli[l], m = eli[LL + l];

    float4 u0 = *(const float4*)(g_x5 + (size_t)u * 8);
    float4 u1 = *(const float4*)(g_x5 + (size_t)u * 8 + 4);
    float4 m0 = *(const float4*)(g_x5 + (size_t)m * 8);
    float4 m1 = *(const float4*)(g_x5 + (size_t)m * 8 + 4);
    float4 a0 = *(const float4*)(ela + (size_t)l * 8);
    float4 a1 = *(const float4*)(ela + (size_t)l * 8 + 4);
    float xu[8] = { u0.x, u0.y, u0.z, u0.w, u1.x, u1.y, u1.z, u1.w };
    float xm[8] = { m0.x, m0.y, m0.z, m0.w, m1.x, m1.y, m1.z, m1.w };
    float ev[8] = { a0.x, a0.y, a0.z, a0.w, a1.x, a1.y, a1.z, a1.w };

    float dot = 0.f;
    #pragma unroll
    for (int j = 0; j < 8; j++) {
        float fu = Bs[j];
        #pragma unroll
        for (int k = 0; k < 8; k++) fu = fmaf(xu[k], Ws[k * 8 + j], fu);
        #pragma unroll
        for (int k = 0; k < 8; k++) fu = fmaf(ev[k], Ws[(8 + k) * 8 + j], fu);
        dot = fmaf(fu, xm[j], dot);
    }
    outp[l] = 1.f / (1.f + expf(-dot));
}

// ---------------- launch -------------------------------------------------------
extern "C" void kernel_launch(void* const* d_in, const int* in_sizes, int n_in,
                              void* d_out, int out_size)
{
    const int*   node_ids = (const int*)d_in[0];
    const int*   ei   = (const int*)d_in[1];
    const int*   eli  = (const int*)d_in[2];
    const float* ea   = (const float*)d_in[4];
    const float* ela  = (const float*)d_in[5];
    const float* emb  = (const float*)d_in[6];
    const float* W1   = (const float*)d_in[7];
    const float* as1  = (const float*)d_in[8];
    const float* ad1  = (const float*)d_in[9];
    const float* We1  = (const float*)d_in[10];
    const float* ae1  = (const float*)d_in[11];
    const float* b1   = (const float*)d_in[12];
    const float* l1W  = (const float*)d_in[13];
    const float* l1b  = (const float*)d_in[14];
    const float* W2   = (const float*)d_in[15];
    const float* as2  = (const float*)d_in[16];
    const float* ad2  = (const float*)d_in[17];
    const float* We2  = (const float*)d_in[18];
    const float* ae2  = (const float*)d_in[19];
    const float* b2   = (const float*)d_in[20];
    const float* l5W  = (const float*)d_in[21];
    const float* l5b  = (const float*)d_in[22];
    const float* cW   = (const float*)d_in[23];
    const float* cb   = (const float*)d_in[24];
    float* out = (float*)d_out;

    const int* srce = ei;
    const int* dste = ei + EE;

    const int GB_NODE = (NN + 31) / 32;            // 1563
    const int GB_EDGE = (EE + 255) / 256;          // 3125
    const int GB_WARP = (NN * 32 + 255) / 256;     // 6250 (warp per node)
    const int GB_N256 = (NN + 255) / 256;          // 196

    // CSR build (shared by both layers)
    k_zero_deg<<<GB_N256, 256>>>();
    k_hist<<<GB_EDGE, 256>>>(dste);
    k_scan<<<1, 1024>>>();
    k_scatter<<<GB_EDGE, 256>>>(srce, dste);

    k_precompute<<<1, 256>>>(W1, as1, ad1, We1, ae1, 0);
    k_precompute<<<1, 256>>>(W2, as2, ad2, We2, ae2, 1);

    // ---- layer 1 ----
    k_node<<<GB_NODE, 256>>>(emb, node_ids, W1, 0);
    k_edge_alpha<<<GB_EDGE, 256>>>(ea, 0);
    k_softmax<<<GB_WARP, 256>>>();
    k_agg_csr<<<GB_WARP, 256>>>();
    k_epi<32><<<(NN + 7) / 8, 256>>>(b1, l1W, l1b);

    // ---- layer 2 ----
    k_node<<<GB_NODE, 256>>>(nullptr, nullptr, W2, 1);
    k_edge_alpha<<<GB_EDGE, 256>>>(ea, 1);
    k_softmax<<<GB_WARP, 256>>>();
    k_agg_csr<<<GB_WARP, 256>>>();
    k_epi<8><<<(NN + 31) / 32, 256>>>(b2, l5W, l5b);

    // ---- classifier ----
    k_clf<<<(LL + 255) / 256, 256>>>(eli, ela, cW, cb, out);
}

// round 3
// speedup vs baseline: 1.4563x; 1.2486x over previous
#include <cuda_runtime.h>
#include <cuda_fp16.h>
#include <math.h>

#define NN  50000   // nodes
#define EE  800000  // edges
#define LL  100000  // label edges
#define HH  8       // heads
#define FD  32      // hidden
#define HC  256     // H*C

// ---------------- scratch (device globals) --------------------------------------
__device__ float  g_x[NN * FD];           // node features entering a GAT layer
__device__ __half g_hh[(size_t)NN * HC];  // h = x @ W  (fp16 storage)
__device__ float  g_alsrc[NN * HH];
__device__ float  g_aldst[NN * HH];
__device__ float  g_alpha[(size_t)EE * HH]; // partial alpha (CSR order) -> normalized w
__device__ float  g_agg[(size_t)NN * HC];
__device__ float  g_x5[NN * HH];
__device__ float  g_Psrc[2][FD * HH];
__device__ float  g_Pdst[2][FD * HH];
__device__ float  g_M[2][HH * HH];
// CSR by destination
__device__ int g_deg[NN];
__device__ int g_rowptr[NN + 1];
__device__ int g_cursor[NN];
__device__ int g_srcp[EE];   // src node per CSR slot
__device__ int g_slot[EE];   // CSR slot per original edge (inverse permutation)

// ---------------- tiny precompute: P_src, P_dst [32,8], M [8,8] ---------------
__global__ void k_precompute(const float* __restrict__ W,
                             const float* __restrict__ a_s,
                             const float* __restrict__ a_d,
                             const float* __restrict__ We,
                             const float* __restrict__ a_e,
                             int layer)
{
    int t = threadIdx.x;           // 256 threads
    int f = t >> 3, h = t & 7;
    float ss = 0.f, sd = 0.f;
    #pragma unroll 8
    for (int c = 0; c < FD; c++) {
        float w = W[f * HC + h * FD + c];
        ss = fmaf(w, a_s[h * FD + c], ss);
        sd = fmaf(w, a_d[h * FD + c], sd);
    }
    g_Psrc[layer][f * HH + h] = ss;
    g_Pdst[layer][f * HH + h] = sd;
    if (t < 64) {
        int k = t >> 3;
        float sm = 0.f;
        #pragma unroll 8
        for (int c = 0; c < FD; c++)
            sm = fmaf(We[k * HC + h * FD + c], a_e[h * FD + c], sm);
        g_M[layer][k * HH + h] = sm;
    }
}

// ---------------- CSR build -----------------------------------------------------
__global__ void k_zero_deg(void) {
    int i = blockIdx.x * 256 + threadIdx.x;
    if (i < NN) g_deg[i] = 0;
}
__global__ void k_hist(const int* __restrict__ dst) {
    int e = blockIdx.x * 256 + threadIdx.x;
    if (e < EE) atomicAdd(&g_deg[dst[e]], 1);
}
__global__ void __launch_bounds__(1024)
k_scan(void) {
    const int CH = (NN + 1023) / 1024;   // 49
    __shared__ int sums[1024];
    int t = threadIdx.x;
    int base = t * CH;
    int s = 0;
    for (int i = 0; i < CH; i++) {
        int idx = base + i;
        if (idx < NN) s += g_deg[idx];
    }
    sums[t] = s;
    __syncthreads();
    for (int off = 1; off < 1024; off <<= 1) {
        int v = (t >= off) ? sums[t - off] : 0;
        __syncthreads();
        sums[t] += v;
        __syncthreads();
    }
    int run = (t > 0) ? sums[t - 1] : 0;   // exclusive prefix of this chunk
    for (int i = 0; i < CH; i++) {
        int idx = base + i;
        if (idx < NN) {
            g_rowptr[idx] = run;
            g_cursor[idx] = run;
            run += g_deg[idx];
        }
    }
    if (t == 1023) g_rowptr[NN] = run;
}
__global__ void k_scatter(const int* __restrict__ src, const int* __restrict__ dst) {
    int e = blockIdx.x * 256 + threadIdx.x;
    if (e >= EE) return;
    int d = dst[e];
    int slot = atomicAdd(&g_cursor[d], 1);
    g_srcp[slot] = src[e];   // scattered store
    g_slot[e]    = slot;     // coalesced store
}

// ---------------- node transform: h = x@W (fp16), al_src/al_dst ----------------
__global__ void __launch_bounds__(256)
k_node(const float* __restrict__ xin, const int* __restrict__ ids,
       const float* __restrict__ W, int layer)
{
    __shared__ float Ws[FD * HC];      // 32KB
    __shared__ float xs[32 * 36];      // 32 nodes, padded stride 36
    __shared__ float Ps[FD * HH], Pd[FD * HH];
    int t  = threadIdx.x;
    int n0 = blockIdx.x * 32;

    for (int i = t; i < FD * HC; i += 256) Ws[i] = W[i];
    Ps[t] = g_Psrc[layer][t];
    Pd[t] = g_Pdst[layer][t];
    const float* xp = xin ? xin : g_x;
    for (int i = t; i < 32 * FD; i += 256) {
        int n = i >> 5, k = i & 31;
        int node = n0 + n;
        float v = 0.f;
        if (node < NN) {
            int r = ids ? ids[node] : node;
            v = xp[(size_t)r * FD + k];
        }
        xs[n * 36 + k] = v;
    }
    __syncthreads();

    float acc[32];
    #pragma unroll
    for (int n = 0; n < 32; n++) acc[n] = 0.f;
    #pragma unroll
    for (int kk = 0; kk < 8; kk++) {
        float w0 = Ws[(kk * 4 + 0) * HC + t];
        float w1 = Ws[(kk * 4 + 1) * HC + t];
        float w2 = Ws[(kk * 4 + 2) * HC + t];
        float w3 = Ws[(kk * 4 + 3) * HC + t];
        #pragma unroll
        for (int n = 0; n < 32; n++) {
            float4 xv = *(const float4*)&xs[n * 36 + kk * 4];
            acc[n] = fmaf(xv.x, w0, acc[n]);
            acc[n] = fmaf(xv.y, w1, acc[n]);
            acc[n] = fmaf(xv.z, w2, acc[n]);
            acc[n] = fmaf(xv.w, w3, acc[n]);
        }
    }
    #pragma unroll
    for (int n = 0; n < 32; n++)
        if (n0 + n < NN) g_hh[(size_t)(n0 + n) * HC + t] = __float2half(acc[n]);

    {
        int n = t >> 3, h = t & 7;
        if (n0 + n < NN) {
            float ss = 0.f, sd = 0.f;
            #pragma unroll
            for (int k = 0; k < FD; k++) {
                float xv = xs[n * 36 + k];
                ss = fmaf(xv, Ps[k * HH + h], ss);
                sd = fmaf(xv, Pd[k * HH + h], sd);
            }
            g_alsrc[(n0 + n) * HH + h] = ss;
            g_aldst[(n0 + n) * HH + h] = sd;
        }
    }
}

// ---------------- edge partial: alpha_p = al_src[src] + ea@M -> CSR slot --------
__global__ void __launch_bounds__(256)
k_edge_partial(const int* __restrict__ src, const float* __restrict__ ea, int layer)
{
    __shared__ float Ms[64];
    if (threadIdx.x < 64) Ms[threadIdx.x] = g_M[layer][threadIdx.x];
    __syncthreads();
    int e = blockIdx.x * 256 + threadIdx.x;
    if (e >= EE) return;
    int s = src[e];
    int p = g_slot[e];

    float4 e0 = *(const float4*)(ea + (size_t)e * 8);       // coalesced
    float4 e1 = *(const float4*)(ea + (size_t)e * 8 + 4);
    float4 s0 = *(const float4*)(g_alsrc + (size_t)s * 8);  // gather 32B
    float4 s1 = *(const float4*)(g_alsrc + (size_t)s * 8 + 4);

    float al[8] = { s0.x, s0.y, s0.z, s0.w, s1.x, s1.y, s1.z, s1.w };
    float ev[8] = { e0.x, e0.y, e0.z, e0.w, e1.x, e1.y, e1.z, e1.w };
    #pragma unroll
    for (int k = 0; k < 8; k++)
        #pragma unroll
        for (int h = 0; h < 8; h++)
            al[h] = fmaf(ev[k], Ms[k * 8 + h], al[h]);

    *(float4*)(g_alpha + (size_t)p * 8)     = make_float4(al[0], al[1], al[2], al[3]);
    *(float4*)(g_alpha + (size_t)p * 8 + 4) = make_float4(al[4], al[5], al[6], al[7]);
}

// ---------------- per-node softmax (adds al_dst + lrelu, then normalize) --------
__global__ void __launch_bounds__(256)
k_softmax(void)
{
    int n    = (blockIdx.x * 256 + threadIdx.x) >> 5;
    int lane = threadIdx.x & 31;
    if (n >= NN) return;
    int r0 = g_rowptr[n], r1 = g_rowptr[n + 1];
    int deg = r1 - r0;
    if (deg == 0) return;

    int h  = lane & 7;       // head
    int eg = lane >> 3;      // edge group 0..3

    float aldl = (lane < 8) ? g_aldst[(size_t)n * 8 + lane] : 0.f;
    float ald  = __shfl_sync(0xffffffffu, aldl, h);

    // pass 1: per-head max
    float m = -INFINITY;
    for (int i = eg; i < deg; i += 4) {
        float a = g_alpha[(size_t)(r0 + i) * 8 + h] + ald;
        a = a > 0.f ? a : 0.2f * a;
        m = fmaxf(m, a);
    }
    m = fmaxf(m, __shfl_xor_sync(0xffffffffu, m, 8));
    m = fmaxf(m, __shfl_xor_sync(0xffffffffu, m, 16));

    // pass 2: denom
    float s = 0.f;
    for (int i = eg; i < deg; i += 4) {
        float a = g_alpha[(size_t)(r0 + i) * 8 + h] + ald;
        a = a > 0.f ? a : 0.2f * a;
        s += expf(a - m);
    }
    s += __shfl_xor_sync(0xffffffffu, s, 8);
    s += __shfl_xor_sync(0xffffffffu, s, 16);
    float rinv = 1.f / (s + 1e-16f);

    // pass 3: write normalized weights
    for (int i = eg; i < deg; i += 4) {
        size_t idx = (size_t)(r0 + i) * 8 + h;
        float a = g_alpha[idx] + ald;
        a = a > 0.f ? a : 0.2f * a;
        g_alpha[idx] = expf(a - m) * rinv;
    }
}

// ---------------- heavy: agg[n] = sum h[src]*w   (warp per node, 4-edge MLP) ----
__global__ void __launch_bounds__(256)
k_agg_csr(void)
{
    int n    = (blockIdx.x * 256 + threadIdx.x) >> 5;
    int lane = threadIdx.x & 31;
    if (n >= NN) return;
    int r0 = g_rowptr[n], r1 = g_rowptr[n + 1];

    int head = lane >> 2;                 // lane covers cols lane*8 .. lane*8+7 (one head)
    float acc0 = 0.f, acc1 = 0.f, acc2 = 0.f, acc3 = 0.f;
    float acc4 = 0.f, acc5 = 0.f, acc6 = 0.f, acc7 = 0.f;

    for (int p = r0; p < r1; p += 4) {
        int cnt = r1 - p;
        int   sj[4];
        float wj[4];
        #pragma unroll
        for (int j = 0; j < 4; j++) {
            int pp = (j < cnt) ? (p + j) : p;
            sj[j] = g_srcp[pp];
            float w = (lane < 8) ? g_alpha[(size_t)pp * 8 + lane] : 0.f;
            wj[j] = (j < cnt) ? w : 0.f;
        }
        // issue all gathers back-to-back (MLP=4 per lane)
        uint4 v[4];
        #pragma unroll
        for (int j = 0; j < 4; j++)
            v[j] = *(const uint4*)(g_hh + (size_t)sj[j] * HC + lane * 8);
        #pragma unroll
        for (int j = 0; j < 4; j++) {
            float w = __shfl_sync(0xffffffffu, wj[j], head);
            float2 f0 = __half22float2(*(const __half2*)&v[j].x);
            float2 f1 = __half22float2(*(const __half2*)&v[j].y);
            float2 f2 = __half22float2(*(const __half2*)&v[j].z);
            float2 f3 = __half22float2(*(const __half2*)&v[j].w);
            acc0 = fmaf(f0.x, w, acc0); acc1 = fmaf(f0.y, w, acc1);
            acc2 = fmaf(f1.x, w, acc2); acc3 = fmaf(f1.y, w, acc3);
            acc4 = fmaf(f2.x, w, acc4); acc5 = fmaf(f2.y, w, acc5);
            acc6 = fmaf(f3.x, w, acc6); acc7 = fmaf(f3.y, w, acc7);
        }
    }
    float* po = g_agg + (size_t)n * HC + lane * 8;
    *(float4*)(po)     = make_float4(acc0, acc1, acc2, acc3);
    *(float4*)(po + 4) = make_float4(acc4, acc5, acc6, acc7);
}

// ---------------- epilogue: y = relu(agg + b) @ LW + lb ------------------------
template <int NJ>
__global__ void __launch_bounds__(256)
k_epi(const float* __restrict__ bias, const float* __restrict__ LW,
      const float* __restrict__ lb)
{
    constexpr int NODES = 256 / NJ;
    __shared__ float rows[NODES][260];
    __shared__ float LWs[HC * NJ];
    int t  = threadIdx.x;
    int n0 = blockIdx.x * NODES;

    for (int i = t; i < HC * NJ; i += 256) LWs[i] = LW[i];
    for (int i = t; i < NODES * HC; i += 256) {
        int n = i >> 8, c = i & 255;
        float v = 0.f;
        if (n0 + n < NN) v = g_agg[(size_t)(n0 + n) * HC + c] + bias[c];
        rows[n][c] = fmaxf(v, 0.f);
    }
    __syncthreads();

    int n = t / NJ, j = t % NJ;
    if (n0 + n < NN) {
        float acc = lb[j];
        #pragma unroll 8
        for (int c = 0; c < HC; c++)
            acc = fmaf(rows[n][c], LWs[c * NJ + j], acc);
        if (NJ == 32) g_x [(size_t)(n0 + n) * 32 + j] = acc;
        else          g_x5[(size_t)(n0 + n) * 8  + j] = acc;
    }
}

// ---------------- classifier over label edges ---------------------------------
__global__ void __launch_bounds__(256)
k_clf(const int* __restrict__ eli, const float* __restrict__ ela,
      const float* __restrict__ cW, const float* __restrict__ cb,
      float* __restrict__ outp)
{
    __shared__ float Ws[128], Bs[8];
    if (threadIdx.x < 128) Ws[threadIdx.x] = cW[threadIdx.x];
    if (threadIdx.x < 8)   Bs[threadIdx.x] = cb[threadIdx.x];
    __syncthreads();
    int l = blockIdx.x * 256 + threadIdx.x;
    if (l >= LL) return;
    int u = eli[l], m = eli[LL + l];

    float4 u0 = *(const float4*)(g_x5 + (size_t)u * 8);
    float4 u1 = *(const float4*)(g_x5 + (size_t)u * 8 + 4);
    float4 m0 = *(const float4*)(g_x5 + (size_t)m * 8);
    float4 m1 = *(const float4*)(g_x5 + (size_t)m * 8 + 4);
    float4 a0 = *(const float4*)(ela + (size_t)l * 8);
    float4 a1 = *(const float4*)(ela + (size_t)l * 8 + 4);
    float xu[8] = { u0.x, u0.y, u0.z, u0.w, u1.x, u1.y, u1.z, u1.w };
    float xm[8] = { m0.x, m0.y, m0.z, m0.w, m1.x, m1.y, m1.z, m1.w };
    float ev[8] = { a0.x, a0.y, a0.z, a0.w, a1.x, a1.y, a1.z, a1.w };

    float dot = 0.f;
    #pragma unroll
    for (int j = 0; j < 8; j++) {
        float fu = Bs[j];
        #pragma unroll
        for (int k = 0; k < 8; k++) fu = fmaf(xu[k], Ws[k * 8 + j], fu);
        #pragma unroll
        for (int k = 0; k < 8; k++) fu = fmaf(ev[k], Ws[(8 + k) * 8 + j], fu);
        dot = fmaf(fu, xm[j], dot);
    }
    outp[l] = 1.f / (1.f + expf(-dot));
}

// ---------------- launch -------------------------------------------------------
extern "C" void kernel_launch(void* const* d_in, const int* in_sizes, int n_in,
                              void* d_out, int out_size)
{
    const int*   node_ids = (const int*)d_in[0];
    const int*   ei   = (const int*)d_in[1];
    const int*   eli  = (const int*)d_in[2];
    const float* ea   = (const float*)d_in[4];
    const float* ela  = (const float*)d_in[5];
    const float* emb  = (const float*)d_in[6];
    const float* W1   = (const float*)d_in[7];
    const float* as1  = (const float*)d_in[8];
    const float* ad1  = (const float*)d_in[9];
    const float* We1  = (const float*)d_in[10];
    const float* ae1  = (const float*)d_in[11];
    const float* b1   = (const float*)d_in[12];
    const float* l1W  = (const float*)d_in[13];
    const float* l1b  = (const float*)d_in[14];
    const float* W2   = (const float*)d_in[15];
    const float* as2  = (const float*)d_in[16];
    const float* ad2  = (const float*)d_in[17];
    const float* We2  = (const float*)d_in[18];
    const float* ae2  = (const float*)d_in[19];
    const float* b2   = (const float*)d_in[20];
    const float* l5W  = (const float*)d_in[21];
    const float* l5b  = (const float*)d_in[22];
    const float* cW   = (const float*)d_in[23];
    const float* cb   = (const float*)d_in[24];
    float* out = (float*)d_out;

    const int* srce = ei;
    const int* dste = ei + EE;

    const int GB_NODE = (NN + 31) / 32;            // 1563
    const int GB_EDGE = (EE + 255) / 256;          // 3125
    const int GB_WARP = (NN * 32 + 255) / 256;     // 6250 (warp per node)
    const int GB_N256 = (NN + 255) / 256;          // 196

    // CSR build (shared by both layers)
    k_zero_deg<<<GB_N256, 256>>>();
    k_hist<<<GB_EDGE, 256>>>(dste);
    k_scan<<<1, 1024>>>();
    k_scatter<<<GB_EDGE, 256>>>(srce, dste);

    k_precompute<<<1, 256>>>(W1, as1, ad1, We1, ae1, 0);
    k_precompute<<<1, 256>>>(W2, as2, ad2, We2, ae2, 1);

    // ---- layer 1 ----
    k_node<<<GB_NODE, 256>>>(emb, node_ids, W1, 0);
    k_edge_partial<<<GB_EDGE, 256>>>(srce, ea, 0);
    k_softmax<<<GB_WARP, 256>>>();
    k_agg_csr<<<GB_WARP, 256>>>();
    k_epi<32><<<(NN + 7) / 8, 256>>>(b1, l1W, l1b);

    // ---- layer 2 ----
    k_node<<<GB_NODE, 256>>>(nullptr, nullptr, W2, 1);
    k_edge_partial<<<GB_EDGE, 256>>>(srce, ea, 1);
    k_softmax<<<GB_WARP, 256>>>();
    k_agg_csr<<<GB_WARP, 256>>>();
    k_epi<8><<<(NN + 31) / 32, 256>>>(b2, l5W, l5b);

    // ---- classifier ----
    k_clf<<<(LL + 255) / 256, 256>>>(eli, ela, cW, cb, out);
}